// round 3
// baseline (speedup 1.0000x reference)
#include <cuda_runtime.h>
#include <math.h>

// Problem constants
#define BSZ 64
#define SEQ 512
#define DIM 768
#define NSPANS 1280
#define LMAX 5
#define H 200
#define G4 800          // 4*H
#define NENT 16
#define MROWS (NSPANS*LMAX)   // 6400

// Scratch (device globals; no allocation allowed). Referenced directly from
// device code — kernel_launch performs NO CUDA API calls except launches.
__device__ float d_x    [2ll * MROWS * DIM];    // gathered inputs, fwd + rev
__device__ float d_xg   [2ll * MROWS * G4];     // input-gate preactivations
__device__ float d_gates[2ll * NSPANS * G4];    // per-step gates
__device__ float d_h    [2ll * NSPANS * H];
__device__ float d_c    [2ll * NSPANS * H];
__device__ float d_sum  [2ll * NSPANS * H];

// ---------------------------------------------------------------------------
// Gather: x[dir][n][l][:] = hidden[batch[n], tok[n, l or len-1-l], :] masked
// ---------------------------------------------------------------------------
__global__ void gather_kernel(const float* __restrict__ hidden,
                              const int* __restrict__ tok,
                              const int* __restrict__ slen,
                              const int* __restrict__ sbatch)
{
    int row = blockIdx.x;              // 0 .. 2*6400-1
    int d4  = threadIdx.x;             // 0 .. 191 (float4 lanes)
    int dir = row / MROWS;
    int r   = row - dir * MROWS;
    int n   = r / LMAX;
    int l   = r - n * LMAX;
    int ln  = slen[n];

    float4 v = make_float4(0.f, 0.f, 0.f, 0.f);
    if (l < ln) {
        int sl = dir ? (ln - 1 - l) : l;
        int t  = tok[n * LMAX + sl];
        int b  = sbatch[n];
        v = *(const float4*)(hidden + ((size_t)b * SEQ + t) * DIM + d4 * 4);
    }
    *(float4*)(d_x + (size_t)row * DIM + d4 * 4) = v;
}

// ---------------------------------------------------------------------------
// Generic fp32 GEMM body: C[M,N] = A[M,K] @ W[N,K]^T (+ b1 + b2)(+ Cadd)
// BM=128, BN=64, BK=16, 256 threads, 8x4 microtile.
// ---------------------------------------------------------------------------
#define BM 128
#define BN 64
#define BK 16
#define TM 8
#define TN 4

template <bool HAS_BIAS, bool HAS_ADD>
__device__ __forceinline__
void gemm_body(const float* __restrict__ A, int lda,
               const float* __restrict__ W, int ldw,
               const float* __restrict__ b1, const float* __restrict__ b2,
               const float* __restrict__ Cadd, int ldadd,
               float* __restrict__ C, int ldc,
               int M, int N, int K)
{
    __shared__ float As[BK][BM + 4];
    __shared__ float Bs[BK][BN + 4];

    int tid = threadIdx.x;
    int tx = tid & 15;           // 0..15 -> N direction
    int ty = tid >> 4;           // 0..15 -> M direction
    int m0 = blockIdx.y * BM;
    int n0 = blockIdx.x * BN;

    float acc[TM][TN];
#pragma unroll
    for (int i = 0; i < TM; i++)
#pragma unroll
        for (int j = 0; j < TN; j++) acc[i][j] = 0.f;

    int ar = tid >> 2;           // 0..63
    int ac = (tid & 3) * 4;      // 0,4,8,12

    for (int kt = 0; kt < K; kt += BK) {
        // Load A tile (2 rows per thread), transposed into As[k][m]
#pragma unroll
        for (int rr = 0; rr < 2; rr++) {
            int m = m0 + ar + rr * 64;
            int k = kt + ac;
            float4 v = make_float4(0.f, 0.f, 0.f, 0.f);
            if (m < M && k < K)
                v = *(const float4*)(A + (size_t)m * lda + k);
            As[ac + 0][ar + rr * 64] = v.x;
            As[ac + 1][ar + rr * 64] = v.y;
            As[ac + 2][ar + rr * 64] = v.z;
            As[ac + 3][ar + rr * 64] = v.w;
        }
        // Load B tile
        {
            int nn = n0 + ar;
            int k = kt + ac;
            float4 v = make_float4(0.f, 0.f, 0.f, 0.f);
            if (nn < N && k < K)
                v = *(const float4*)(W + (size_t)nn * ldw + k);
            Bs[ac + 0][ar] = v.x;
            Bs[ac + 1][ar] = v.y;
            Bs[ac + 2][ar] = v.z;
            Bs[ac + 3][ar] = v.w;
        }
        __syncthreads();

#pragma unroll
        for (int k = 0; k < BK; k++) {
            float a[TM], bb[TN];
            *(float4*)&a[0] = *(float4*)&As[k][ty * TM];
            *(float4*)&a[4] = *(float4*)&As[k][ty * TM + 4];
            *(float4*)&bb[0] = *(float4*)&Bs[k][tx * TN];
#pragma unroll
            for (int i = 0; i < TM; i++)
#pragma unroll
                for (int j = 0; j < TN; j++)
                    acc[i][j] = fmaf(a[i], bb[j], acc[i][j]);
        }
        __syncthreads();
    }

#pragma unroll
    for (int i = 0; i < TM; i++) {
        int m = m0 + ty * TM + i;
        if (m >= M) continue;
#pragma unroll
        for (int j = 0; j < TN; j++) {
            int n = n0 + tx * TN + j;
            if (n >= N) continue;
            float v = acc[i][j];
            if (HAS_BIAS) v += b1[n] + b2[n];
            if (HAS_ADD)  v += Cadd[(size_t)m * ldadd + n];
            C[(size_t)m * ldc + n] = v;
        }
    }
}

// xg = x @ W_ih^T + b_ih + b_hh, both dirs via blockIdx.z
__global__ __launch_bounds__(256)
void gemm_xg_kernel(const float* __restrict__ Wf, const float* __restrict__ bif,
                    const float* __restrict__ bhf,
                    const float* __restrict__ Wb, const float* __restrict__ bib,
                    const float* __restrict__ bhb)
{
    int dir = blockIdx.z;
    const float* W  = dir ? Wb : Wf;
    const float* b1 = dir ? bib : bif;
    const float* b2 = dir ? bhb : bhf;
    gemm_body<true, false>(d_x + (size_t)dir * MROWS * DIM, DIM,
                           W, DIM, b1, b2, nullptr, 0,
                           d_xg + (size_t)dir * MROWS * G4, G4,
                           MROWS, G4, DIM);
}

// gates = h @ W_hh^T + xg[:, t, :], both dirs via blockIdx.z
__global__ __launch_bounds__(256)
void gemm_hh_kernel(const float* __restrict__ Wf, const float* __restrict__ Wb,
                    int t)
{
    int dir = blockIdx.z;
    const float* W = dir ? Wb : Wf;
    gemm_body<false, true>(d_h + (size_t)dir * NSPANS * H, H,
                           W, H, nullptr, nullptr,
                           d_xg + (size_t)dir * MROWS * G4 + (size_t)t * G4,
                           LMAX * G4,
                           d_gates + (size_t)dir * NSPANS * G4, G4,
                           NSPANS, G4, H);
}

// ---------------------------------------------------------------------------
// LSTM cell pointwise update (both dirs in one launch)
// FROM_XG: t==0 path reads gates straight from xg (h=0 -> gates = xg row t=0)
// ---------------------------------------------------------------------------
__device__ __forceinline__ float sigm(float x) { return 1.f / (1.f + expf(-x)); }

__global__ void lstm_cell(const int* __restrict__ slen, int t)
{
    int idx = blockIdx.x * blockDim.x + threadIdx.x;
    if (idx >= 2 * NSPANS * H) return;
    int hh  = idx % H;
    int n   = (idx / H) % NSPANS;
    int dir = idx / (H * NSPANS);

    const float* row;
    if (t == 0)
        row = d_xg + (size_t)dir * MROWS * G4 + (size_t)n * (LMAX * G4); // t=0 slice
    else
        row = d_gates + (size_t)dir * NSPANS * G4 + (size_t)n * G4;

    float gi = row[hh];
    float gf = row[H + hh];
    float gg = row[2 * H + hh];
    float go = row[3 * H + hh];

    float cprev = (t == 0) ? 0.f : d_c[idx];
    float cn = sigm(gf) * cprev + sigm(gi) * tanhf(gg);
    float hn = sigm(go) * tanhf(cn);
    d_c[idx] = cn;
    d_h[idx] = hn;

    float m = (t < slen[n]) ? hn : 0.f;
    d_sum[idx] = (t == 0) ? m : (d_sum[idx] + m);
}

// ---------------------------------------------------------------------------
// Logits: out[n][e] = sum_f[n] . E[e][0:200] + sum_b[n] . E[e][200:400]
// ---------------------------------------------------------------------------
__global__ void logits_kernel(const float* __restrict__ E,
                              float* __restrict__ out)
{
    int idx = blockIdx.x * blockDim.x + threadIdx.x;
    if (idx >= NSPANS * NENT) return;
    int e = idx % NENT;
    int n = idx / NENT;

    const float4* sf = (const float4*)(d_sum + (size_t)n * H);
    const float4* sb = (const float4*)(d_sum + (size_t)NSPANS * H + (size_t)n * H);
    const float4* er = (const float4*)(E + (size_t)e * 2 * H);

    float acc = 0.f;
#pragma unroll
    for (int j = 0; j < H / 4; j++) {
        float4 a = sf[j], b = er[j];
        acc += a.x * b.x + a.y * b.y + a.z * b.z + a.w * b.w;
    }
#pragma unroll
    for (int j = 0; j < H / 4; j++) {
        float4 a = sb[j], b = er[H / 4 + j];
        acc += a.x * b.x + a.y * b.y + a.z * b.z + a.w * b.w;
    }
    out[idx] = acc;
}

// ---------------------------------------------------------------------------
// Launch — kernel launches only, no other CUDA API calls.
// ---------------------------------------------------------------------------
extern "C" void kernel_launch(void* const* d_in, const int* in_sizes, int n_in,
                              void* d_out, int out_size)
{
    const float* hidden = (const float*)d_in[0];
    const int*   tok    = (const int*)d_in[1];
    const int*   slen   = (const int*)d_in[2];
    const int*   sbatch = (const int*)d_in[3];
    const float* W_ih_f = (const float*)d_in[4];
    const float* W_hh_f = (const float*)d_in[5];
    const float* b_ih_f = (const float*)d_in[6];
    const float* b_hh_f = (const float*)d_in[7];
    const float* W_ih_b = (const float*)d_in[8];
    const float* W_hh_b = (const float*)d_in[9];
    const float* b_ih_b = (const float*)d_in[10];
    const float* b_hh_b = (const float*)d_in[11];
    const float* E      = (const float*)d_in[12];
    float* out          = (float*)d_out;

    // 1. Gather + mask + reverse
    gather_kernel<<<2 * MROWS, DIM / 4>>>(hidden, tok, slen, sbatch);

    // 2. xg = x @ W_ih^T + b_ih + b_hh, both dirs
    {
        dim3 grid((G4 + BN - 1) / BN, (MROWS + BM - 1) / BM, 2);
        gemm_xg_kernel<<<grid, 256>>>(W_ih_f, b_ih_f, b_hh_f,
                                      W_ih_b, b_ih_b, b_hh_b);
    }

    // 3. Recurrence
    const int cell_threads = 256;
    const int cell_blocks  = (2 * NSPANS * H + cell_threads - 1) / cell_threads;
    lstm_cell<<<cell_blocks, cell_threads>>>(slen, 0);

    for (int t = 1; t < LMAX; t++) {
        dim3 grid((G4 + BN - 1) / BN, (NSPANS + BM - 1) / BM, 2);
        gemm_hh_kernel<<<grid, 256>>>(W_hh_f, W_hh_b, t);
        lstm_cell<<<cell_blocks, cell_threads>>>(slen, t);
    }

    // 4. Logits
    logits_kernel<<<(NSPANS * NENT + 127) / 128, 128>>>(E, out);
}

// round 4
// speedup vs baseline: 1.8641x; 1.8641x over previous
#include <cuda_runtime.h>
#include <math.h>
#include <stdint.h>

// Problem constants
#define BSZ 64
#define SEQ 512
#define DIM 768
#define NSPANS 1280
#define LMAX 5
#define H 200
#define G4 800          // 4*H
#define NENT 16
#define MROWS (NSPANS*LMAX)   // 6400

// Scratch (device globals)
__device__ float d_x    [2ll * MROWS * DIM];
__device__ float d_xg   [2ll * MROWS * G4];
__device__ float d_gates[2ll * NSPANS * G4];
__device__ float d_h    [2ll * NSPANS * H];
__device__ float d_c    [2ll * NSPANS * H];
__device__ float d_sum  [2ll * NSPANS * H];

// ---------------------------------------------------------------------------
// Gather: x[dir][n][l][:] = hidden[batch[n], tok[n, l or len-1-l], :] masked
// ---------------------------------------------------------------------------
__global__ void gather_kernel(const float* __restrict__ hidden,
                              const int* __restrict__ tok,
                              const int* __restrict__ slen,
                              const int* __restrict__ sbatch)
{
    int row = blockIdx.x;
    int d4  = threadIdx.x;             // 0..191
    int dir = row / MROWS;
    int r   = row - dir * MROWS;
    int n   = r / LMAX;
    int l   = r - n * LMAX;
    int ln  = slen[n];

    float4 v = make_float4(0.f, 0.f, 0.f, 0.f);
    if (l < ln) {
        int sl = dir ? (ln - 1 - l) : l;
        int t  = tok[n * LMAX + sl];
        int b  = sbatch[n];
        v = *(const float4*)(hidden + ((size_t)b * SEQ + t) * DIM + d4 * 4);
    }
    *(float4*)(d_x + (size_t)row * DIM + d4 * 4) = v;
}

// ---------------------------------------------------------------------------
// tf32 tensor-core GEMM: C[M,N] = A[M,K] @ W[N,K]^T (+b1+b2)(+Cadd)
// mma.sync.m16n8k8 tf32. 256 threads = 8 warps.
// ---------------------------------------------------------------------------
#define BK 32
#define PAD 4
#define LDSROW (BK + PAD)   // 36: conflict-free fragment loads

__device__ __forceinline__ uint32_t f2tf32(float f) {
    uint32_t r;
    asm("cvt.rna.tf32.f32 %0, %1;" : "=r"(r) : "f"(f));
    return r;
}

__device__ __forceinline__ void mma_tf32(float* c, const uint32_t* a, const uint32_t* b) {
    asm volatile(
        "mma.sync.aligned.m16n8k8.row.col.f32.tf32.tf32.f32 "
        "{%0,%1,%2,%3}, {%4,%5,%6,%7}, {%8,%9}, {%0,%1,%2,%3};"
        : "+f"(c[0]), "+f"(c[1]), "+f"(c[2]), "+f"(c[3])
        : "r"(a[0]), "r"(a[1]), "r"(a[2]), "r"(a[3]), "r"(b[0]), "r"(b[1]));
}

template <int BM, int BN, int WM, int WN, bool HAS_BIAS, bool HAS_ADD>
__device__ __forceinline__
void gemm_tc(const float* __restrict__ A, int lda,
             const float* __restrict__ W, int ldw,
             const float* __restrict__ b1, const float* __restrict__ b2,
             const float* __restrict__ Cadd, int ldadd,
             float* __restrict__ C, int ldc,
             int M, int N, int K)
{
    constexpr int WTM = BM / WM;     // warp tile M
    constexpr int WTN = BN / WN;     // warp tile N
    constexpr int MT  = WTM / 16;    // m16 tiles per warp
    constexpr int NT  = WTN / 8;     // n8 tiles per warp

    __shared__ uint32_t As[BM][LDSROW];
    __shared__ uint32_t Bs[BN][LDSROW];

    int tid  = threadIdx.x;
    int warp = tid >> 5;
    int lane = tid & 31;
    int wm   = warp % WM;
    int wn   = warp / WM;
    int grp  = lane >> 2;    // 0..7
    int qid  = lane & 3;     // 0..3
    int m0   = blockIdx.y * BM;
    int n0   = blockIdx.x * BN;

    float acc[MT][NT][4];
#pragma unroll
    for (int i = 0; i < MT; i++)
#pragma unroll
        for (int j = 0; j < NT; j++)
#pragma unroll
            for (int q = 0; q < 4; q++) acc[i][j][q] = 0.f;

    const int lrow = tid >> 3;          // 0..31
    const int lcol = (tid & 7) * 4;     // 0,4,...,28

    for (int kt = 0; kt < K; kt += BK) {
        // Load + convert A tile: BM x BK
#pragma unroll
        for (int p = 0; p < BM / 32; p++) {
            int m = lrow + p * 32;
            int k = kt + lcol;
            float4 v = make_float4(0.f, 0.f, 0.f, 0.f);
            if (k < K)
                v = *(const float4*)(A + (size_t)(m0 + m) * lda + k);
            uint4 t;
            t.x = f2tf32(v.x); t.y = f2tf32(v.y);
            t.z = f2tf32(v.z); t.w = f2tf32(v.w);
            *(uint4*)&As[m][lcol] = t;
        }
        // Load + convert B tile: BN x BK  (W is [N][K] row-major)
#pragma unroll
        for (int p = 0; p < BN / 32; p++) {
            int n = lrow + p * 32;
            int k = kt + lcol;
            float4 v = make_float4(0.f, 0.f, 0.f, 0.f);
            if ((n0 + n) < N && k < K)
                v = *(const float4*)(W + (size_t)(n0 + n) * ldw + k);
            uint4 t;
            t.x = f2tf32(v.x); t.y = f2tf32(v.y);
            t.z = f2tf32(v.z); t.w = f2tf32(v.w);
            *(uint4*)&Bs[n][lcol] = t;
        }
        __syncthreads();

#pragma unroll
        for (int ks = 0; ks < BK / 8; ks++) {
            uint32_t af[MT][4], bf[NT][2];
#pragma unroll
            for (int i = 0; i < MT; i++) {
                int mr = wm * WTM + i * 16;
                af[i][0] = As[mr + grp    ][ks * 8 + qid    ];
                af[i][1] = As[mr + grp + 8][ks * 8 + qid    ];
                af[i][2] = As[mr + grp    ][ks * 8 + qid + 4];
                af[i][3] = As[mr + grp + 8][ks * 8 + qid + 4];
            }
#pragma unroll
            for (int j = 0; j < NT; j++) {
                int nr = wn * WTN + j * 8;
                bf[j][0] = Bs[nr + grp][ks * 8 + qid    ];
                bf[j][1] = Bs[nr + grp][ks * 8 + qid + 4];
            }
#pragma unroll
            for (int i = 0; i < MT; i++)
#pragma unroll
                for (int j = 0; j < NT; j++)
                    mma_tf32(acc[i][j], af[i], bf[j]);
        }
        __syncthreads();
    }

    // Epilogue
#pragma unroll
    for (int i = 0; i < MT; i++) {
#pragma unroll
        for (int j = 0; j < NT; j++) {
            int m = m0 + wm * WTM + i * 16 + grp;
            int n = n0 + wn * WTN + j * 8 + qid * 2;
            if (n < N) {
                float add0 = 0.f, add1 = 0.f, add2 = 0.f, add3 = 0.f;
                if (HAS_BIAS) {
                    float bb0 = b1[n] + b2[n];
                    float bb1 = b1[n + 1] + b2[n + 1];
                    add0 += bb0; add1 += bb1; add2 += bb0; add3 += bb1;
                }
                if (HAS_ADD) {
                    add0 += Cadd[(size_t)m * ldadd + n];
                    add1 += Cadd[(size_t)m * ldadd + n + 1];
                    add2 += Cadd[(size_t)(m + 8) * ldadd + n];
                    add3 += Cadd[(size_t)(m + 8) * ldadd + n + 1];
                }
                C[(size_t)m * ldc + n]           = acc[i][j][0] + add0;
                C[(size_t)m * ldc + n + 1]       = acc[i][j][1] + add1;
                C[(size_t)(m + 8) * ldc + n]     = acc[i][j][2] + add2;
                C[(size_t)(m + 8) * ldc + n + 1] = acc[i][j][3] + add3;
            }
        }
    }
}

// xg = x @ W_ih^T + b_ih + b_hh  (dirs via blockIdx.z). BM=128,BN=64, 4x2 warps.
__global__ __launch_bounds__(256)
void gemm_xg_kernel(const float* __restrict__ Wf, const float* __restrict__ bif,
                    const float* __restrict__ bhf,
                    const float* __restrict__ Wb, const float* __restrict__ bib,
                    const float* __restrict__ bhb)
{
    int dir = blockIdx.z;
    const float* W  = dir ? Wb : Wf;
    const float* c1 = dir ? bib : bif;
    const float* c2 = dir ? bhb : bhf;
    gemm_tc<128, 64, 4, 2, true, false>(
        d_x + (size_t)dir * MROWS * DIM, DIM,
        W, DIM, c1, c2, nullptr, 0,
        d_xg + (size_t)dir * MROWS * G4, G4,
        MROWS, G4, DIM);
}

// gates = h @ W_hh^T + xg[:, t, :]  (dirs via blockIdx.z). BM=64,BN=64, 2x4 warps.
__global__ __launch_bounds__(256)
void gemm_hh_kernel(const float* __restrict__ Wf, const float* __restrict__ Wb,
                    int t)
{
    int dir = blockIdx.z;
    const float* W = dir ? Wb : Wf;
    gemm_tc<64, 64, 2, 4, false, true>(
        d_h + (size_t)dir * NSPANS * H, H,
        W, H, nullptr, nullptr,
        d_xg + (size_t)dir * MROWS * G4 + (size_t)t * G4, LMAX * G4,
        d_gates + (size_t)dir * NSPANS * G4, G4,
        NSPANS, G4, H);
}

// ---------------------------------------------------------------------------
// LSTM cell pointwise update
// ---------------------------------------------------------------------------
__device__ __forceinline__ float sigm(float x) { return 1.f / (1.f + expf(-x)); }

__global__ void lstm_cell(const int* __restrict__ slen, int t)
{
    int idx = blockIdx.x * blockDim.x + threadIdx.x;
    if (idx >= 2 * NSPANS * H) return;
    int hh  = idx % H;
    int n   = (idx / H) % NSPANS;
    int dir = idx / (H * NSPANS);

    const float* row;
    if (t == 0)
        row = d_xg + (size_t)dir * MROWS * G4 + (size_t)n * (LMAX * G4);
    else
        row = d_gates + (size_t)dir * NSPANS * G4 + (size_t)n * G4;

    float gi = row[hh];
    float gf = row[H + hh];
    float gg = row[2 * H + hh];
    float go = row[3 * H + hh];

    float cprev = (t == 0) ? 0.f : d_c[idx];
    float cn = sigm(gf) * cprev + sigm(gi) * tanhf(gg);
    float hn = sigm(go) * tanhf(cn);
    d_c[idx] = cn;
    d_h[idx] = hn;

    float m = (t < slen[n]) ? hn : 0.f;
    d_sum[idx] = (t == 0) ? m : (d_sum[idx] + m);
}

// ---------------------------------------------------------------------------
// Logits
// ---------------------------------------------------------------------------
__global__ void logits_kernel(const float* __restrict__ E,
                              float* __restrict__ out)
{
    int idx = blockIdx.x * blockDim.x + threadIdx.x;
    if (idx >= NSPANS * NENT) return;
    int e = idx % NENT;
    int n = idx / NENT;

    const float4* sf = (const float4*)(d_sum + (size_t)n * H);
    const float4* sb = (const float4*)(d_sum + (size_t)NSPANS * H + (size_t)n * H);
    const float4* er = (const float4*)(E + (size_t)e * 2 * H);

    float acc = 0.f;
#pragma unroll
    for (int j = 0; j < H / 4; j++) {
        float4 a = sf[j], b = er[j];
        acc += a.x * b.x + a.y * b.y + a.z * b.z + a.w * b.w;
    }
#pragma unroll
    for (int j = 0; j < H / 4; j++) {
        float4 a = sb[j], b = er[H / 4 + j];
        acc += a.x * b.x + a.y * b.y + a.z * b.z + a.w * b.w;
    }
    out[idx] = acc;
}

// ---------------------------------------------------------------------------
// Launch — kernel launches only.
// ---------------------------------------------------------------------------
extern "C" void kernel_launch(void* const* d_in, const int* in_sizes, int n_in,
                              void* d_out, int out_size)
{
    const float* hidden = (const float*)d_in[0];
    const int*   tok    = (const int*)d_in[1];
    const int*   slen   = (const int*)d_in[2];
    const int*   sbatch = (const int*)d_in[3];
    const float* W_ih_f = (const float*)d_in[4];
    const float* W_hh_f = (const float*)d_in[5];
    const float* b_ih_f = (const float*)d_in[6];
    const float* b_hh_f = (const float*)d_in[7];
    const float* W_ih_b = (const float*)d_in[8];
    const float* W_hh_b = (const float*)d_in[9];
    const float* b_ih_b = (const float*)d_in[10];
    const float* b_hh_b = (const float*)d_in[11];
    const float* E      = (const float*)d_in[12];
    float* out          = (float*)d_out;

    // 1. Gather + mask + reverse
    gather_kernel<<<2 * MROWS, DIM / 4>>>(hidden, tok, slen, sbatch);

    // 2. xg GEMM (both dirs)
    {
        dim3 grid((G4 + 63) / 64, MROWS / 128, 2);   // 13 x 50 x 2
        gemm_xg_kernel<<<grid, 256>>>(W_ih_f, b_ih_f, b_hh_f,
                                      W_ih_b, b_ih_b, b_hh_b);
    }

    // 3. Recurrence
    const int cell_threads = 256;
    const int cell_blocks  = (2 * NSPANS * H + cell_threads - 1) / cell_threads;
    lstm_cell<<<cell_blocks, cell_threads>>>(slen, 0);

    for (int t = 1; t < LMAX; t++) {
        dim3 grid((G4 + 63) / 64, NSPANS / 64, 2);   // 13 x 20 x 2
        gemm_hh_kernel<<<grid, 256>>>(W_hh_f, W_hh_b, t);
        lstm_cell<<<cell_blocks, cell_threads>>>(slen, t);
    }

    // 4. Logits
    logits_kernel<<<(NSPANS * NENT + 127) / 128, 128>>>(E, out);
}